// round 3
// baseline (speedup 1.0000x reference)
#include <cuda_runtime.h>
#include <math.h>

#define B_ 256
#define N_ 36
#define F_ 2048
#define L_ 26
#define A_ 512
#define E_ 1024
#define D_ 1024
#define V_ 10000
#define T_ 25
#define G_ 4096   // 4*D

// ---------------- static device scratch (no allocation allowed) ----------------
__device__ __align__(256) float g_fs[(size_t)B_ * N_ * F_];      // sorted feats
__device__ __align__(256) float g_favg[B_ * F_];
__device__ __align__(256) float g_favgW[B_ * G_];                // favg @ Wf^T + td_b
__device__ __align__(256) float g_ebd[(size_t)B_ * T_ * E_];     // gathered embeddings
__device__ __align__(256) float g_xe1[(size_t)B_ * T_ * G_];     // precomputed LSTM1 input-gate part
__device__ __align__(256) float g_imgatt[(size_t)B_ * N_ * A_];
__device__ __align__(256) float g_h1[B_ * D_], g_c1[B_ * D_], g_h2[B_ * D_], g_c2[B_ * D_];
__device__ __align__(256) float g_arh[B_ * D_], g_arc[B_ * D_], g_prevh1[B_ * D_];
__device__ __align__(256) float g_h1n[B_ * D_], g_c1n[B_ * D_], g_h2n[B_ * D_], g_c2n[B_ * D_];
__device__ __align__(256) float g_arhn[B_ * D_], g_arcn[B_ * D_];
__device__ __align__(256) float g_gates1[B_ * G_], g_gates2[B_ * G_], g_gates3[B_ * G_];
__device__ __align__(256) float g_q[B_ * A_];
__device__ __align__(256) float g_aw[B_ * F_];
__device__ __align__(256) float g_H2[(size_t)B_ * T_ * D_];
__device__ __align__(256) float g_ARHN[(size_t)B_ * T_ * D_];
__device__ __align__(256) float g_PREV[(size_t)B_ * T_ * D_];
__device__ __align__(256) float g_ARL[(size_t)B_ * T_ * D_];
__device__ __align__(256) float g_rowss[B_ * T_];
__device__ int g_order[B_];
__device__ int g_declen[B_];
__device__ unsigned char g_act[B_ * T_];

// ---------------- small helpers ----------------
__device__ __forceinline__ float sigm(float x) { return 1.f / (1.f + expf(-x)); }

// ---------------- setup kernels ----------------
__global__ void sort_k(const int* __restrict__ sizes) {
    __shared__ int s[B_];
    int i = threadIdx.x;
    s[i] = sizes[i];
    __syncthreads();
    int my = s[i];
    int rank = 0;
    for (int j = 0; j < B_; ++j) {
        int sj = s[j];
        if (sj > my || (sj == my && j < i)) rank++;
    }
    g_order[rank] = i;
    g_declen[rank] = my - 1;
}

__global__ void init_act_k() {
    int idx = blockIdx.x * blockDim.x + threadIdx.x;
    if (idx < B_ * T_) {
        int b = idx / T_, t = idx - b * T_;
        g_act[idx] = (t < g_declen[b]) ? 1 : 0;
    }
}

__global__ void zero_carries_k() {
    int idx = blockIdx.x * blockDim.x + threadIdx.x;
    if (idx < B_ * D_) {
        g_h1[idx] = 0.f; g_c1[idx] = 0.f; g_h2[idx] = 0.f; g_c2[idx] = 0.f;
        g_arh[idx] = 0.f; g_arc[idx] = 0.f; g_prevh1[idx] = 0.f;
    }
}

__global__ void gather_fs_k(const float4* __restrict__ feats) {
    const int per_b = N_ * F_ / 4;
    size_t total = (size_t)B_ * per_b;
    for (size_t i = (size_t)blockIdx.x * blockDim.x + threadIdx.x; i < total;
         i += (size_t)gridDim.x * blockDim.x) {
        int b = (int)(i / per_b);
        size_t rem = i - (size_t)b * per_b;
        ((float4*)g_fs)[i] = feats[(size_t)g_order[b] * per_b + rem];
    }
}

__global__ void favg_k() {
    int idx = blockIdx.x * blockDim.x + threadIdx.x;
    if (idx < B_ * F_) {
        int b = idx / F_, f = idx - b * F_;
        const float* base = g_fs + (size_t)b * N_ * F_ + f;
        float s = 0.f;
        #pragma unroll
        for (int n = 0; n < N_; ++n) s += base[(size_t)n * F_];
        g_favg[idx] = s * (1.f / N_);
    }
}

__global__ void gather_ebd_k(const int* __restrict__ seqs, const float4* __restrict__ emb) {
    const int per_r = E_ / 4;  // 256
    size_t total = (size_t)B_ * T_ * per_r;
    for (size_t i = (size_t)blockIdx.x * blockDim.x + threadIdx.x; i < total;
         i += (size_t)gridDim.x * blockDim.x) {
        int r = (int)(i / per_r);
        int e4 = (int)(i - (size_t)r * per_r);
        int b = r / T_, t = r - b * T_;
        int sid = seqs[g_order[b] * L_ + t];
        ((float4*)g_ebd)[i] = emb[(size_t)sid * per_r + e4];
    }
}

// xe1 += favgW[b] (td_b already folded into favgW via bias)
__global__ void add_favg_k() {
    const int per_r = G_ / 4;  // 1024
    size_t total = (size_t)B_ * T_ * per_r;
    for (size_t i = (size_t)blockIdx.x * blockDim.x + threadIdx.x; i < total;
         i += (size_t)gridDim.x * blockDim.x) {
        int r = (int)(i / per_r);
        int g4 = (int)(i - (size_t)r * per_r);
        int b = r / T_;
        float4 x = ((float4*)g_xe1)[i];
        float4 a = ((const float4*)g_favgW)[(size_t)b * per_r + g4];
        x.x += a.x; x.y += a.y; x.z += a.z; x.w += a.w;
        ((float4*)g_xe1)[i] = x;
    }
}

// ---------------- generic fp32 GEMM: C[M,N] = A[M,K] @ W[N,K]^T (+ init/bias/mask) ----------------
__global__ void gemm_k(float* __restrict__ C,
                       const float* __restrict__ Cinit, int initLd,
                       const float* __restrict__ A,
                       const float* __restrict__ W, int ldw,
                       const float* __restrict__ bias,
                       const unsigned char* __restrict__ mask,
                       int M, int N, int K, int accum) {
    __shared__ __align__(16) float As[16][64];
    __shared__ __align__(16) float Bs[16][64];
    const int bm = blockIdx.y * 64, bn = blockIdx.x * 64;
    const int tid = threadIdx.x;
    const int tx = tid & 15, ty = tid >> 4;
    const int lrow = tid >> 2, lk = (tid & 3) * 4;
    float acc[4][4] = {};
    for (int k0 = 0; k0 < K; k0 += 16) {
        float4 av = make_float4(0.f, 0.f, 0.f, 0.f);
        float4 bv = make_float4(0.f, 0.f, 0.f, 0.f);
        int am = bm + lrow;
        if (am < M) av = *(const float4*)(A + (size_t)am * K + k0 + lk);
        int wn = bn + lrow;
        if (wn < N) bv = *(const float4*)(W + (size_t)wn * ldw + k0 + lk);
        __syncthreads();
        As[lk][lrow] = av.x; As[lk + 1][lrow] = av.y; As[lk + 2][lrow] = av.z; As[lk + 3][lrow] = av.w;
        Bs[lk][lrow] = bv.x; Bs[lk + 1][lrow] = bv.y; Bs[lk + 2][lrow] = bv.z; Bs[lk + 3][lrow] = bv.w;
        __syncthreads();
        #pragma unroll
        for (int k = 0; k < 16; ++k) {
            float4 a4 = *(const float4*)(&As[k][ty * 4]);
            float4 b4 = *(const float4*)(&Bs[k][tx * 4]);
            acc[0][0] += a4.x * b4.x; acc[0][1] += a4.x * b4.y; acc[0][2] += a4.x * b4.z; acc[0][3] += a4.x * b4.w;
            acc[1][0] += a4.y * b4.x; acc[1][1] += a4.y * b4.y; acc[1][2] += a4.y * b4.z; acc[1][3] += a4.y * b4.w;
            acc[2][0] += a4.z * b4.x; acc[2][1] += a4.z * b4.y; acc[2][2] += a4.z * b4.z; acc[2][3] += a4.z * b4.w;
            acc[3][0] += a4.w * b4.x; acc[3][1] += a4.w * b4.y; acc[3][2] += a4.w * b4.z; acc[3][3] += a4.w * b4.w;
        }
    }
    #pragma unroll
    for (int i = 0; i < 4; ++i) {
        int m = bm + ty * 4 + i;
        if (m >= M) continue;
        #pragma unroll
        for (int j = 0; j < 4; ++j) {
            int n = bn + tx * 4 + j;
            if (n >= N) continue;
            size_t ci = (size_t)m * N + n;
            float v = acc[i][j];
            if (accum) {
                C[ci] += v;
            } else {
                if (bias) v += bias[n];
                if (Cinit) v += Cinit[(size_t)m * initLd + n];
                if (mask) v = mask[m] ? v : 0.f;
                C[ci] = v;
            }
        }
    }
}

// ---------------- LSTM elementwise ----------------
__device__ __forceinline__ void lstm_elem(const float* __restrict__ gates,
                                          const float* __restrict__ c_old,
                                          float* __restrict__ h_new,
                                          float* __restrict__ c_new, int idx) {
    int b = idx / D_, d = idx - b * D_;
    const float* g = gates + (size_t)b * G_;
    float ig = sigm(g[d]);
    float fg = sigm(g[D_ + d]);
    float gg = tanhf(g[2 * D_ + d]);
    float og = sigm(g[3 * D_ + d]);
    float c = fg * c_old[idx] + ig * gg;
    c_new[idx] = c;
    h_new[idx] = og * tanhf(c);
}

__global__ void lstm1_ew_k() {
    int idx = blockIdx.x * blockDim.x + threadIdx.x;
    if (idx < B_ * D_) lstm_elem(g_gates1, g_c1, g_h1n, g_c1n, idx);
}
__global__ void lstm2_ew_k(int t) {
    int idx = blockIdx.x * blockDim.x + threadIdx.x;
    if (idx < B_ * D_) {
        lstm_elem(g_gates2, g_c2, g_h2n, g_c2n, idx);
        int b = idx / D_, d = idx - b * D_;
        g_H2[((size_t)b * T_ + t) * D_ + d] = g_h2n[idx];
    }
}
__global__ void lstm3_ew_k(int t) {
    int idx = blockIdx.x * blockDim.x + threadIdx.x;
    if (idx < B_ * D_) {
        lstm_elem(g_gates3, g_arc, g_arhn, g_arcn, idx);
        int b = idx / D_, d = idx - b * D_;
        g_ARHN[((size_t)b * T_ + t) * D_ + d] = g_arhn[idx];
    }
}

// ---------------- attention: scores -> softmax -> weighted feature sum ----------------
__global__ void attn_k(const float* __restrict__ attw, const float* __restrict__ attb) {
    int b = blockIdx.x;
    int tid = threadIdx.x;
    int warp = tid >> 5, lane = tid & 31;
    __shared__ float s_q[A_];
    __shared__ float s_w[A_];
    __shared__ float s_sc[N_];
    __shared__ float s_alpha[N_];
    for (int i = tid; i < A_; i += 256) { s_q[i] = g_q[b * A_ + i]; s_w[i] = attw[i]; }
    __syncthreads();
    for (int n = warp; n < N_; n += 8) {
        const float* row = g_imgatt + ((size_t)b * N_ + n) * A_;
        float p = 0.f;
        for (int a = lane; a < A_; a += 32) {
            float v = s_q[a] + row[a];
            p += fmaxf(v, 0.f) * s_w[a];
        }
        #pragma unroll
        for (int o = 16; o; o >>= 1) p += __shfl_xor_sync(0xffffffffu, p, o);
        if (lane == 0) s_sc[n] = p + attb[0];
    }
    __syncthreads();
    if (warp == 0) {
        float v0 = s_sc[lane];
        float v1 = (lane + 32 < N_) ? s_sc[lane + 32] : -1e30f;
        float mx = fmaxf(v0, v1);
        #pragma unroll
        for (int o = 16; o; o >>= 1) mx = fmaxf(mx, __shfl_xor_sync(0xffffffffu, mx, o));
        float e0 = expf(v0 - mx);
        float e1 = (lane + 32 < N_) ? expf(v1 - mx) : 0.f;
        float s = e0 + e1;
        #pragma unroll
        for (int o = 16; o; o >>= 1) s += __shfl_xor_sync(0xffffffffu, s, o);
        s_alpha[lane] = e0 / s;
        if (lane + 32 < N_) s_alpha[lane + 32] = e1 / s;
    }
    __syncthreads();
    for (int f = tid; f < F_; f += 256) {
        float acc = 0.f;
        const float* fb = g_fs + (size_t)b * N_ * F_ + f;
        #pragma unroll
        for (int n = 0; n < N_; ++n) acc += s_alpha[n] * fb[(size_t)n * F_];
        g_aw[b * F_ + f] = acc;
    }
}

// ---------------- masked carry commit (+ record prev_h1 used this step) ----------------
__global__ void commit_k(int t) {
    int idx = blockIdx.x * blockDim.x + threadIdx.x;
    if (idx >= B_ * D_) return;
    int b = idx / D_, d = idx - b * D_;
    g_PREV[((size_t)b * T_ + t) * D_ + d] = g_prevh1[idx];
    if (g_act[b * T_ + t]) {
        g_h1[idx] = g_h1n[idx];  g_c1[idx] = g_c1n[idx];
        g_h2[idx] = g_h2n[idx];  g_c2[idx] = g_c2n[idx];
        g_arh[idx] = g_arhn[idx]; g_arc[idx] = g_arcn[idx];
        g_prevh1[idx] = g_h1n[idx];
    }
}

// ---------------- loss ----------------
__global__ void loss_rows_k() {
    int r = blockIdx.x;       // r = b*T + t
    int t = r % T_;
    int tid = threadIdx.x;
    float p = 0.f;
    if (t > 0 && g_act[r]) {
        const float* a = g_ARL + (size_t)r * D_;
        const float* pv = g_PREV + (size_t)r * D_;
        for (int d = tid; d < D_; d += 256) { float df = a[d] - pv[d]; p += df * df; }
    }
    __shared__ float sred[256];
    sred[tid] = p;
    __syncthreads();
    for (int o = 128; o; o >>= 1) { if (tid < o) sred[tid] += sred[tid + o]; __syncthreads(); }
    if (tid == 0) g_rowss[r] = sred[0];
}

__global__ void loss_final_k(float* __restrict__ out) {
    __shared__ float ss[256], sc[256];
    int tid = threadIdx.x;
    float total = 0.f;
    for (int t = 1; t < T_; ++t) {
        float s = 0.f, c = 0.f;
        for (int b = tid; b < B_; b += 256) {
            s += g_rowss[b * T_ + t];
            c += g_act[b * T_ + t] ? 1.f : 0.f;
        }
        ss[tid] = s; sc[tid] = c;
        __syncthreads();
        for (int o = 128; o; o >>= 1) { if (tid < o) { ss[tid] += ss[tid + o]; sc[tid] += sc[tid + o]; } __syncthreads(); }
        if (tid == 0) total += ss[0] / fmaxf(sc[0], 1.f) * 0.005f;
        __syncthreads();
    }
    if (tid == 0) out[(size_t)B_ * T_ * V_] = total;
}

// ---------------- host ----------------
static inline float* fsym(const void* s) { void* p = nullptr; cudaGetSymbolAddress(&p, s); return (float*)p; }

static inline void launch_gemm(float* C, const float* Cinit, int initLd,
                               const float* A, const float* W, int ldw,
                               const float* bias, const unsigned char* mask,
                               int M, int N, int K, int accum) {
    dim3 grid((N + 63) / 64, (M + 63) / 64);
    gemm_k<<<grid, 256>>>(C, Cinit, initLd, A, W, ldw, bias, mask, M, N, K, accum);
}

extern "C" void kernel_launch(void* const* d_in, const int* in_sizes, int n_in,
                              void* d_out, int out_size) {
    const float* feats     = (const float*)d_in[0];
    const int*   sequences = (const int*)d_in[1];
    const int*   sizes     = (const int*)d_in[2];
    const float* emb       = (const float*)d_in[3];
    const float* td_wih    = (const float*)d_in[4];
    const float* td_whh    = (const float*)d_in[5];
    const float* td_b      = (const float*)d_in[6];
    const float* lang_wih  = (const float*)d_in[7];
    const float* lang_whh  = (const float*)d_in[8];
    const float* lang_b    = (const float*)d_in[9];
    const float* attf_w    = (const float*)d_in[10];
    const float* attf_b    = (const float*)d_in[11];
    const float* attd_w    = (const float*)d_in[12];
    const float* attd_b    = (const float*)d_in[13];
    const float* att_w     = (const float*)d_in[14];
    const float* att_b     = (const float*)d_in[15];
    const float* out_w     = (const float*)d_in[16];
    const float* out_b     = (const float*)d_in[17];
    const float* ar_wih    = (const float*)d_in[18];
    const float* ar_whh    = (const float*)d_in[19];
    const float* ar_b      = (const float*)d_in[20];
    const float* arl_w     = (const float*)d_in[21];
    const float* arl_b     = (const float*)d_in[22];
    float* out = (float*)d_out;

    float* p_fs     = fsym(g_fs);
    float* p_favg   = fsym(g_favg);
    float* p_favgW  = fsym(g_favgW);
    float* p_ebd    = fsym(g_ebd);
    float* p_xe1    = fsym(g_xe1);
    float* p_imgatt = fsym(g_imgatt);
    float* p_h1     = fsym(g_h1);
    float* p_h2     = fsym(g_h2);
    float* p_h1n    = fsym(g_h1n);
    float* p_arh    = fsym(g_arh);
    float* p_aw     = fsym(g_aw);
    float* p_q      = fsym(g_q);
    float* p_gates1 = fsym(g_gates1);
    float* p_gates2 = fsym(g_gates2);
    float* p_gates3 = fsym(g_gates3);
    float* p_H2     = fsym(g_H2);
    float* p_ARHN   = fsym(g_ARHN);
    float* p_ARL    = fsym(g_ARL);
    void* p_act_v = nullptr; cudaGetSymbolAddress(&p_act_v, g_act);
    const unsigned char* p_act = (const unsigned char*)p_act_v;

    // ---- setup ----
    sort_k<<<1, B_>>>(sizes);
    init_act_k<<<(B_ * T_ + 255) / 256, 256>>>();
    zero_carries_k<<<(B_ * D_ + 255) / 256, 256>>>();
    gather_fs_k<<<2048, 256>>>((const float4*)feats);
    favg_k<<<(B_ * F_ + 255) / 256, 256>>>();
    gather_ebd_k<<<2048, 256>>>(sequences, (const float4*)emb);

    // favgW = favg @ Wf^T + td_b        (Wf = td_wih cols [D, D+F))
    launch_gemm(p_favgW, nullptr, 0, p_favg, td_wih + D_, G_, td_b, nullptr, B_, G_, F_, 0);
    // xe1 = ebd @ We^T                  (We = td_wih cols [D+F, D+F+E))
    launch_gemm(p_xe1, nullptr, 0, p_ebd, td_wih + D_ + F_, G_, nullptr, nullptr, B_ * T_, G_, E_, 0);
    add_favg_k<<<4096, 256>>>();
    // img_att = fs @ attf_w^T + attf_b
    launch_gemm(p_imgatt, nullptr, 0, p_fs, attf_w, F_, attf_b, nullptr, B_ * N_, A_, F_, 0);

    // ---- sequential decode steps ----
    for (int t = 0; t < T_; ++t) {
        // gates1 = xe1[:,t,:] + h2 @ W_h2^T + h1 @ td_whh^T
        launch_gemm(p_gates1, p_xe1 + (size_t)t * G_, T_ * G_, p_h2, td_wih, G_, nullptr, nullptr, B_, G_, D_, 0);
        launch_gemm(p_gates1, nullptr, 0, p_h1, td_whh, D_, nullptr, nullptr, B_, G_, D_, 1);
        lstm1_ew_k<<<(B_ * D_ + 255) / 256, 256>>>();
        // q = h1n @ attd_w^T + attd_b
        launch_gemm(p_q, nullptr, 0, p_h1n, attd_w, D_, attd_b, nullptr, B_, A_, D_, 0);
        attn_k<<<B_, 256>>>(att_w, att_b);
        // gates2 = aw @ W_aw^T + h1n @ W_h1^T + h2 @ lang_whh^T + lang_b
        launch_gemm(p_gates2, nullptr, 0, p_aw, lang_wih, F_ + D_, lang_b, nullptr, B_, G_, F_, 0);
        launch_gemm(p_gates2, nullptr, 0, p_h1n, lang_wih + F_, F_ + D_, nullptr, nullptr, B_, G_, D_, 1);
        launch_gemm(p_gates2, nullptr, 0, p_h2, lang_whh, D_, nullptr, nullptr, B_, G_, D_, 1);
        lstm2_ew_k<<<(B_ * D_ + 255) / 256, 256>>>(t);
        // gates3 = h1n @ ar_wih^T + arh @ ar_whh^T + ar_b
        launch_gemm(p_gates3, nullptr, 0, p_h1n, ar_wih, D_, ar_b, nullptr, B_, G_, D_, 0);
        launch_gemm(p_gates3, nullptr, 0, p_arh, ar_whh, D_, nullptr, nullptr, B_, G_, D_, 1);
        lstm3_ew_k<<<(B_ * D_ + 255) / 256, 256>>>(t);
        commit_k<<<(B_ * D_ + 255) / 256, 256>>>(t);
    }

    // ---- batched tail ----
    // preds = mask(H2all @ out_w^T + out_b)
    launch_gemm(out, nullptr, 0, p_H2, out_w, D_, out_b, p_act, B_ * T_, V_, D_, 0);
    // ARL = ARHNall @ arl_w^T + arl_b
    launch_gemm(p_ARL, nullptr, 0, p_ARHN, arl_w, D_, arl_b, nullptr, B_ * T_, D_, D_, 0);
    loss_rows_k<<<B_ * T_, 256>>>();
    loss_final_k<<<1, 256>>>(out);
}